// round 1
// baseline (speedup 1.0000x reference)
#include <cuda_runtime.h>
#include <cstdint>
#include <cfloat>

// ---------------------------------------------------------------------------
// AttentionBasedRewiring:
//   q = x@Wq + bq            [N, H]
//   k = x@Wk + bk            [N, H]   (stored transposed as kT [H, N])
//   sim = q @ k^T            [N, N]   (streamed, never materialized)
//   out = (top8 vals [N,8] as f32) ++ (top8 idx [N,8] cast to f32)
//
// Assumed output layout: d_out = float[2*N*8], vals first then indices.
// ---------------------------------------------------------------------------

#define N_NODES 65536
#define D_IN    512
#define HDIM    128
#define TOPK    8
#define BM      128              // rows per CTA (sim kernel)
#define BN      128              // cols per tile
#define NTILES  (N_NODES / BN)   // 512
#define PITCH   136              // smem row pitch in floats (bank-conflict-free)
#define TPB     256

__device__ float g_q [(size_t)N_NODES * HDIM];   // [N][H]
__device__ float g_kT[(size_t)HDIM * N_NODES];   // [H][N]

// ---------------- packed f32x2 helpers (sm_100+ FFMA2 path) ----------------
__device__ __forceinline__ void fma2(unsigned long long& d,
                                     unsigned long long a,
                                     unsigned long long b) {
    asm("fma.rn.f32x2 %0, %1, %2, %0;" : "+l"(d) : "l"(a), "l"(b));
}
__device__ __forceinline__ unsigned long long splat2(float a) {
    unsigned long long r;
    asm("mov.b64 %0, {%1, %1};" : "=l"(r) : "f"(a));
    return r;
}

// ---------------------------------------------------------------------------
// Kernel 1: Q = x@Wq + bq (natural layout), kT = (x@Wk + bk)^T
// grid (N/128, 2): y==0 -> q, y==1 -> kT. 128x128 output tile, 8x8 microtile.
// ---------------------------------------------------------------------------
__global__ __launch_bounds__(256) void qk_kernel(const float* __restrict__ x,
                                                 const float* __restrict__ Wq,
                                                 const float* __restrict__ bq,
                                                 const float* __restrict__ Wk,
                                                 const float* __restrict__ bk) {
    const int zz = blockIdx.y;
    const float* __restrict__ W    = zz ? Wk : Wq;
    const float* __restrict__ bias = zz ? bk : bq;
    const int r0 = blockIdx.x * 128;

    __shared__ float xs[32][PITCH];   // [k][row]  (transposed on load)
    __shared__ float ws[32][PITCH];   // [k][col]

    const int tid = threadIdx.x;
    const int tx = tid & 15;
    const int ty = tid >> 4;

    float acc[8][8];
#pragma unroll
    for (int i = 0; i < 8; ++i)
#pragma unroll
        for (int j = 0; j < 8; ++j) acc[i][j] = 0.f;

    for (int kc = 0; kc < D_IN; kc += 32) {
        // load x tile [128 rows x 32 k], transpose into xs[k][row]
        {
            const int r = tid >> 1, kq = tid & 1;
#pragma unroll
            for (int j = 0; j < 4; ++j) {
                float4 v = *(const float4*)&x[(size_t)(r0 + r) * D_IN + kc + kq * 16 + j * 4];
                const int kk = kq * 16 + j * 4;
                xs[kk + 0][r] = v.x; xs[kk + 1][r] = v.y;
                xs[kk + 2][r] = v.z; xs[kk + 3][r] = v.w;
            }
            const int kr = tid >> 3, cq = tid & 7;
#pragma unroll
            for (int j = 0; j < 4; ++j) {
                *(float4*)&ws[kr][cq * 16 + j * 4] =
                    *(const float4*)&W[(size_t)(kc + kr) * HDIM + cq * 16 + j * 4];
            }
        }
        __syncthreads();

#pragma unroll 8
        for (int k = 0; k < 32; ++k) {
            float4 a0 = *(const float4*)&xs[k][4 * ty];
            float4 a1 = *(const float4*)&xs[k][64 + 4 * ty];
            float4 b0 = *(const float4*)&ws[k][4 * tx];
            float4 b1 = *(const float4*)&ws[k][64 + 4 * tx];
            float av[8] = {a0.x, a0.y, a0.z, a0.w, a1.x, a1.y, a1.z, a1.w};
            float bv[8] = {b0.x, b0.y, b0.z, b0.w, b1.x, b1.y, b1.z, b1.w};
#pragma unroll
            for (int i = 0; i < 8; ++i)
#pragma unroll
                for (int j = 0; j < 8; ++j) acc[i][j] += av[i] * bv[j];
        }
        __syncthreads();
    }

    if (zz == 0) {
        // q natural [row][col]
#pragma unroll
        for (int i = 0; i < 8; ++i) {
            const int rm = (i < 4) ? (4 * ty + i) : (64 + 4 * ty + i - 4);
            float4 o0, o1;
            o0.x = acc[i][0] + bias[4 * tx + 0];
            o0.y = acc[i][1] + bias[4 * tx + 1];
            o0.z = acc[i][2] + bias[4 * tx + 2];
            o0.w = acc[i][3] + bias[4 * tx + 3];
            o1.x = acc[i][4] + bias[64 + 4 * tx + 0];
            o1.y = acc[i][5] + bias[64 + 4 * tx + 1];
            o1.z = acc[i][6] + bias[64 + 4 * tx + 2];
            o1.w = acc[i][7] + bias[64 + 4 * tx + 3];
            *(float4*)&g_q[(size_t)(r0 + rm) * HDIM + 4 * tx]      = o0;
            *(float4*)&g_q[(size_t)(r0 + rm) * HDIM + 64 + 4 * tx] = o1;
        }
    } else {
        // kT transposed [col][row]
#pragma unroll
        for (int j = 0; j < 8; ++j) {
            const int cm = (j < 4) ? (4 * tx + j) : (64 + 4 * tx + j - 4);
            const float bb = bias[cm];
            float4 o0, o1;
            o0.x = acc[0][j] + bb; o0.y = acc[1][j] + bb;
            o0.z = acc[2][j] + bb; o0.w = acc[3][j] + bb;
            o1.x = acc[4][j] + bb; o1.y = acc[5][j] + bb;
            o1.z = acc[6][j] + bb; o1.w = acc[7][j] + bb;
            *(float4*)&g_kT[(size_t)cm * N_NODES + r0 + 4 * ty]      = o0;
            *(float4*)&g_kT[(size_t)cm * N_NODES + r0 + 64 + 4 * ty] = o1;
        }
    }
}

// ---------------------------------------------------------------------------
// Kernel 2: fused sim GEMM + running top-8
// ---------------------------------------------------------------------------
__device__ __forceinline__ void ks_load_async(float* ks, int c0) {
    const int tid = threadIdx.x;
    const int h = tid >> 1, half = tid & 1;
    const float* gsrc = g_kT + (size_t)h * N_NODES + c0;
    uint32_t sbase = (uint32_t)__cvta_generic_to_shared(ks + h * PITCH);
#pragma unroll
    for (int j = 0; j < 16; ++j) {
        const int col = 8 * j + 4 * half;   // bank-conflict-free interleave
        asm volatile("cp.async.cg.shared.global [%0], [%1], 16;"
                     :: "r"(sbase + col * 4), "l"(gsrc + col));
    }
    asm volatile("cp.async.commit_group;");
}

// sorted (desc) top-8 register insert; ties keep earlier (lower) index.
__device__ __forceinline__ void topk_ins(float v, int c, float tv[TOPK], int ti[TOPK]) {
    if (v <= tv[7]) return;
    int pos = 8;
#pragma unroll
    for (int p = 7; p >= 0; --p)
        if (tv[p] < v) pos = p;          // smallest p with tv[p] < v (strict)
#pragma unroll
    for (int p = 7; p > 0; --p)
        if (p > pos) { tv[p] = tv[p - 1]; ti[p] = ti[p - 1]; }
#pragma unroll
    for (int p = 0; p < 8; ++p)
        if (p == pos) { tv[p] = v; ti[p] = c; }
}

__global__ __launch_bounds__(TPB, 1) void sim_topk_kernel(float* __restrict__ out) {
    extern __shared__ float sm[];
    float* qs   = sm;                     // [HDIM][PITCH]  (q tile, transposed [h][row])
    float* ks   = sm + HDIM * PITCH;      // [HDIM][PITCH]  ([h][col])
    float* sims = sm + 2 * HDIM * PITCH;  // [BM][PITCH]

    const int tid = threadIdx.x;
    const int tx = tid & 15;
    const int ty = tid >> 4;
    const int srow  = tid & 127;          // scan: owned row
    const int shalf = tid >> 7;           // scan: col half (0..63 / 64..127)
    const int r0 = blockIdx.x * BM;

    // prologue: q tile -> smem (transposed), async-load ks tile 0
    {
        const int r = tid >> 1, hq = tid & 1;
        const float* qsrc = g_q + (size_t)(r0 + r) * HDIM + hq * 64;
#pragma unroll
        for (int j = 0; j < 16; ++j) {
            float4 v = *(const float4*)(qsrc + j * 4);
            const int h = hq * 64 + j * 4;
            qs[(h + 0) * PITCH + r] = v.x;
            qs[(h + 1) * PITCH + r] = v.y;
            qs[(h + 2) * PITCH + r] = v.z;
            qs[(h + 3) * PITCH + r] = v.w;
        }
    }
    ks_load_async(ks, 0);

    float tv[TOPK];
    int   ti[TOPK];
#pragma unroll
    for (int j = 0; j < TOPK; ++j) { tv[j] = -FLT_MAX; ti[j] = 0; }

    for (int t = 0; t < NTILES; ++t) {
        asm volatile("cp.async.wait_group 0;" ::: "memory");
        __syncthreads();                                  // ks tile t ready

        // ---- GEMM: 128x128 tile, 8x8 microtile, packed f32x2 FMAs ----
        unsigned long long acc[8][4];
#pragma unroll
        for (int i = 0; i < 8; ++i)
#pragma unroll
            for (int p = 0; p < 4; ++p) acc[i][p] = 0ull;

#pragma unroll 4
        for (int h = 0; h < HDIM; ++h) {
            float4 a0 = *(const float4*)&qs[h * PITCH + 4 * ty];
            float4 a1 = *(const float4*)&qs[h * PITCH + 64 + 4 * ty];
            ulonglong2 b0 = *(const ulonglong2*)&ks[h * PITCH + 4 * tx];
            ulonglong2 b1 = *(const ulonglong2*)&ks[h * PITCH + 64 + 4 * tx];
            float av[8] = {a0.x, a0.y, a0.z, a0.w, a1.x, a1.y, a1.z, a1.w};
#pragma unroll
            for (int i = 0; i < 8; ++i) {
                unsigned long long as = splat2(av[i]);
                fma2(acc[i][0], as, b0.x);
                fma2(acc[i][1], as, b0.y);
                fma2(acc[i][2], as, b1.x);
                fma2(acc[i][3], as, b1.y);
            }
        }
        __syncthreads();                                  // done reading ks

        if (t + 1 < NTILES) ks_load_async(ks, (t + 1) * BN);  // prefetch overlaps scan

        // ---- dump sim tile to smem ----
#pragma unroll
        for (int i = 0; i < 8; ++i) {
            const int rm = (i < 4) ? (4 * ty + i) : (64 + 4 * ty + i - 4);
            *(ulonglong2*)&sims[rm * PITCH + 4 * tx]      = make_ulonglong2(acc[i][0], acc[i][1]);
            *(ulonglong2*)&sims[rm * PITCH + 64 + 4 * tx] = make_ulonglong2(acc[i][2], acc[i][3]);
        }
        __syncthreads();                                  // sim visible

        // ---- scan: per (row, half) running top-8 in registers ----
        const int cbase = t * BN + 64 * shalf;
        const float* srp = &sims[srow * PITCH + 64 * shalf];
#pragma unroll
        for (int j4 = 0; j4 < 16; ++j4) {
            float4 v = *(const float4*)(srp + 4 * j4);
            float m = fmaxf(fmaxf(v.x, v.y), fmaxf(v.z, v.w));
            if (m > tv[7]) {
                const int c = cbase + 4 * j4;
                topk_ins(v.x, c + 0, tv, ti);
                topk_ins(v.y, c + 1, tv, ti);
                topk_ins(v.z, c + 2, tv, ti);
                topk_ins(v.w, c + 3, tv, ti);
            }
        }
    }

    // ---- final 2-way merge per row (tie -> lower index, matches lax.top_k) ----
    __syncthreads();
    float* mv = qs;                       // reuse qs region
    int*   mi = (int*)(qs + 128 * 16);
    {
        const int base = (srow * 2 + shalf) * TOPK;
#pragma unroll
        for (int j = 0; j < TOPK; ++j) { mv[base + j] = tv[j]; mi[base + j] = ti[j]; }
    }
    __syncthreads();

    if (tid < 128) {
        const float* va_p = &mv[(tid * 2 + 0) * TOPK];
        const float* vb_p = &mv[(tid * 2 + 1) * TOPK];
        const int*   ia_p = &mi[(tid * 2 + 0) * TOPK];
        const int*   ib_p = &mi[(tid * 2 + 1) * TOPK];
        int pa = 0, pb = 0;
        const size_t g = (size_t)r0 + tid;
#pragma unroll
        for (int j = 0; j < TOPK; ++j) {
            float va = va_p[pa], vb = vb_p[pb];
            int   ia = ia_p[pa], ib = ib_p[pb];
            bool ta = (va > vb) || (va == vb && ia < ib);
            out[g * TOPK + j] = ta ? va : vb;
            out[(size_t)N_NODES * TOPK + g * TOPK + j] = (float)(ta ? ia : ib);
            if (ta) ++pa; else ++pb;
        }
    }
}

// ---------------------------------------------------------------------------
extern "C" void kernel_launch(void* const* d_in, const int* in_sizes, int n_in,
                              void* d_out, int out_size) {
    const float* x  = (const float*)d_in[0];
    const float* Wq = (const float*)d_in[1];
    const float* bq = (const float*)d_in[2];
    const float* Wk = (const float*)d_in[3];
    const float* bk = (const float*)d_in[4];
    float* out = (float*)d_out;

    qk_kernel<<<dim3(N_NODES / 128, 2), 256>>>(x, Wq, bq, Wk, bk);

    const size_t smem = (size_t)3 * HDIM * PITCH * sizeof(float);  // 208,896 B
    cudaFuncSetAttribute(sim_topk_kernel,
                         cudaFuncAttributeMaxDynamicSharedMemorySize, (int)smem);
    sim_topk_kernel<<<N_NODES / BM, TPB, smem>>>(out);
}